// round 10
// baseline (speedup 1.0000x reference)
#include <cuda_runtime.h>
#include <cstdint>

#define BB 4
#define NN 1024
#define INF 256
#define OUTF 256
#define NH 8
#define BN (BB*NN)

// ---------------- scratch (allocation-free) ----------------
__device__ float g_buf[BN*OUTF];    // g = h @ W  (4 MB)
__device__ float p1_buf[BN*OUTF];   // j-half-1 partial (4 MB)
__device__ float ELraw[BN*NH];
__device__ float ERraw[BN*NH];
__device__ float Lbuf[BN*16];       // [exp(el) x8, exp(.2el) x8]
__device__ float Rbuf[BN*16];       // [exp(er) x8, exp(.2er) x8]
__device__ float4 Rv_glob[BN*NH];   // (Rp*c, Rn*c, c, 0) per (b,j,h)

typedef unsigned long long u64;

__device__ __forceinline__ void ffma2(u64& d, u64 a, u64 b) {
    asm("fma.rn.f32x2 %0, %1, %2, %0;" : "+l"(d) : "l"(a), "l"(b));
}
union U2 { u64 u; float2 f; };

__device__ __forceinline__ uint32_t f2tf32(float f) {
    uint32_t r; asm("cvt.rna.tf32.f32 %0, %1;" : "=r"(r) : "f"(f)); return r;
}
__device__ __forceinline__ void mma_tf32(float* d, const uint32_t* a,
                                         const uint32_t* b) {
    asm volatile(
        "mma.sync.aligned.m16n8k8.row.col.f32.tf32.tf32.f32 "
        "{%0,%1,%2,%3}, {%4,%5,%6,%7}, {%8,%9}, {%0,%1,%2,%3};"
        : "+f"(d[0]), "+f"(d[1]), "+f"(d[2]), "+f"(d[3])
        : "r"(a[0]), "r"(a[1]), "r"(a[2]), "r"(a[3]), "r"(b[0]), "r"(b[1]));
}

// ---------------------------------------------------------------------------
// K1: g = X @ W, 64x64 tile, 4x4 micro-tile, f32x2, fused el/er epilogue.
// ---------------------------------------------------------------------------
__global__ __launch_bounds__(256) void k_gemm(const float* __restrict__ X,
                                              const float* __restrict__ W,
                                              const float* __restrict__ aw) {
    __shared__ __align__(16) float2 Xs2[16][64];
    __shared__ __align__(16) float  Ws [16][64];
    const int t = threadIdx.x;
    const int row0 = (blockIdx.x >> 2) * 64;
    const int cb   = (blockIdx.x & 3) * 64;
    const int tx = t & 15, ty = t >> 4;
    const int r0 = ty * 4, c0 = tx * 4;

    u64 acc[4][2];
#pragma unroll
    for (int r = 0; r < 4; r++) { acc[r][0] = 0ull; acc[r][1] = 0ull; }

    const int lr = t >> 2, lk4 = (t & 3) * 4;
    const int wk = t >> 4, wc = (t & 15) * 4;

    for (int k0 = 0; k0 < INF; k0 += 16) {
        float4 xv = *reinterpret_cast<const float4*>(&X[(row0 + lr) * INF + k0 + lk4]);
        float4 wv = *reinterpret_cast<const float4*>(&W[(k0 + wk) * OUTF + cb + wc]);
        __syncthreads();
        Xs2[lk4 + 0][lr] = make_float2(xv.x, xv.x);
        Xs2[lk4 + 1][lr] = make_float2(xv.y, xv.y);
        Xs2[lk4 + 2][lr] = make_float2(xv.z, xv.z);
        Xs2[lk4 + 3][lr] = make_float2(xv.w, xv.w);
        *reinterpret_cast<float4*>(&Ws[wk][wc]) = wv;
        __syncthreads();
#pragma unroll
        for (int kk = 0; kk < 16; kk++) {
            const ulonglong2* xp = reinterpret_cast<const ulonglong2*>(&Xs2[kk][r0]);
            ulonglong2 xa = xp[0], xb = xp[1];
            ulonglong2 wv2 = *reinterpret_cast<const ulonglong2*>(&Ws[kk][c0]);
            ffma2(acc[0][0], xa.x, wv2.x); ffma2(acc[0][1], xa.x, wv2.y);
            ffma2(acc[1][0], xa.y, wv2.x); ffma2(acc[1][1], xa.y, wv2.y);
            ffma2(acc[2][0], xb.x, wv2.x); ffma2(acc[2][1], xb.x, wv2.y);
            ffma2(acc[3][0], xb.y, wv2.x); ffma2(acc[3][1], xb.y, wv2.y);
        }
    }

    const float4* awp = reinterpret_cast<const float4*>(aw);
    float4 aL = awp[tx & 7];
    float4 aR = awp[8 + (tx & 7)];

#pragma unroll
    for (int r = 0; r < 4; r++) {
        U2 a, b; a.u = acc[r][0]; b.u = acc[r][1];
        float4 o = make_float4(a.f.x, a.f.y, b.f.x, b.f.y);
        *reinterpret_cast<float4*>(&g_buf[(row0 + r0 + r) * OUTF + cb + c0]) = o;

        float el = o.x*aL.x + o.y*aL.y + o.z*aL.z + o.w*aL.w;
        float er = o.x*aR.x + o.y*aR.y + o.z*aR.z + o.w*aR.w;
        el += __shfl_xor_sync(0xffffffffu, el, 1);
        el += __shfl_xor_sync(0xffffffffu, el, 2);
        el += __shfl_xor_sync(0xffffffffu, el, 4);
        er += __shfl_xor_sync(0xffffffffu, er, 1);
        er += __shfl_xor_sync(0xffffffffu, er, 2);
        er += __shfl_xor_sync(0xffffffffu, er, 4);
        if ((tx & 7) == 0) {
            int head = (cb >> 5) + (tx >> 3);
            int row = row0 + r0 + r;
            ELraw[row * NH + head] = el;
            ERraw[row * NH + head] = er;
        }
    }
}

// ---------------------------------------------------------------------------
__global__ __launch_bounds__(256) void k_exp() {
    int idx = blockIdx.x * 256 + threadIdx.x;
    int row = idx >> 3, h = idx & 7;
    float el = ELraw[idx], er = ERraw[idx];
    Lbuf[row * 16 + h]     = __expf(el);
    Lbuf[row * 16 + 8 + h] = __expf(0.2f * el);
    Rbuf[row * 16 + h]     = __expf(er);
    Rbuf[row * 16 + 8 + h] = __expf(0.2f * er);
}

// ---------------------------------------------------------------------------
// K2: 1/s[b,j,h]; writes Rv_glob = (Rp*c, Rn*c, c, 0).
// ---------------------------------------------------------------------------
__global__ __launch_bounds__(512) void k_c(const float* __restrict__ adj) {
    __shared__ float ssum[16][32][8];
    const int t = threadIdx.x;
    const int b = blockIdx.x >> 5;
    const int j0 = (blockIdx.x & 31) * 32;
    const int jl = t & 31, ig = t >> 5;

    const float4* rrow = reinterpret_cast<const float4*>(&Rbuf[(b * NN + j0 + jl) * 16]);
    float4 rp0 = rrow[0], rp1 = rrow[1], rn0 = rrow[2], rn1 = rrow[3];
    float EPr[8] = {rp0.x, rp0.y, rp0.z, rp0.w, rp1.x, rp1.y, rp1.z, rp1.w};
    float ENr[8] = {rn0.x, rn0.y, rn0.z, rn0.w, rn1.x, rn1.y, rn1.z, rn1.w};

    float acc[8];
#pragma unroll
    for (int h = 0; h < 8; h++) acc[h] = 0.f;

    const float* adjcol = adj + (size_t)b * NN * NN + j0 + jl;
#pragma unroll 4
    for (int i = ig; i < NN; i += 16) {
        float a = __ldg(adjcol + (size_t)i * NN);
        const float4* lr = reinterpret_cast<const float4*>(&Lbuf[(b * NN + i) * 16]);
        float4 lp0 = __ldg(&lr[0]), lp1 = __ldg(&lr[1]);
        float4 ln0 = __ldg(&lr[2]), ln1 = __ldg(&lr[3]);
        float EPl[8] = {lp0.x, lp0.y, lp0.z, lp0.w, lp1.x, lp1.y, lp1.z, lp1.w};
        float ENl[8] = {ln0.x, ln0.y, ln0.z, ln0.w, ln1.x, ln1.y, ln1.z, ln1.w};
#pragma unroll
        for (int h = 0; h < 8; h++) {
            float p = EPl[h] * EPr[h];
            float q = ENl[h] * ENr[h];
            float w = (p >= 1.0f) ? p : q;
            acc[h] = fmaf(a, w, acc[h]);
        }
    }
#pragma unroll
    for (int h = 0; h < 8; h++) ssum[ig][jl][h] = acc[h];
    __syncthreads();

    if (t < 256) {
        int jl2 = t >> 3, h = t & 7;
        float s = 0.f;
#pragma unroll
        for (int g = 0; g < 16; g++) s += ssum[g][jl2][h];
        float cc = 1.0f / s;
        int row = b * NN + j0 + jl2;
        float Rp = Rbuf[row * 16 + h] * cc;
        float Rn = Rbuf[row * 16 + 8 + h] * cc;
        Rv_glob[row * NH + h] = make_float4(Rp, Rn, cc, 0.f);
    }
}

// ---------------------------------------------------------------------------
// K3 (tensor): A fragments computed in registers; G (B) in smem, double-
// buffered, column-pair-permuted + xor-swizzled for conflict-free LDS.64.
// Grid 512 = (jhalf, b, h, i-tile of 128). 256 thr = 8 warps, warp = 16 rows.
// ---------------------------------------------------------------------------
#define GSTR 40
struct SmemT {
    float  Gh[2][32][GSTR];   // 10.2 KB
    float  Gl[2][32][GSTR];   // 10.2 KB
    float4 Rv_s[2][32];       //  1 KB
};

// perm: within each 8-col kstep group, col c -> unit (c&3)*2 + (c>>2)
__device__ __forceinline__ int gperm(int jj) {
    int k = jj >> 3, c = jj & 7;
    return 8 * k + ((c & 3) * 2 + (c >> 2));
}

__device__ __forceinline__ void stageG(SmemT& sm, int buf, int b, int j0,
                                       int h, int t) {
    int jj = t >> 3, d0 = (t & 7) * 4;
    float4 gv = __ldg(reinterpret_cast<const float4*>(
        g_buf + (size_t)(b * NN + j0 + jj) * OUTF + h * 32 + d0));
    float vs[4] = {gv.x, gv.y, gv.z, gv.w};
    int pu = gperm(jj);
#pragma unroll
    for (int e = 0; e < 4; e++) {
        int d = d0 + e;
        int px = pu ^ (((d >> 4) & 1) << 2);
        uint32_t hb = f2tf32(vs[e]);
        float lo = vs[e] - __uint_as_float(hb);
        sm.Gh[buf][d][px] = __uint_as_float(hb);
        sm.Gl[buf][d][px] = __uint_as_float(f2tf32(lo));
    }
}

__device__ __forceinline__ uint32_t wsplit(float Lp, float Ln, float4 rv,
                                           float a, uint32_t& lo) {
    float p = Lp * rv.x;
    float q = Ln * rv.y;
    float w = a * ((p >= rv.z) ? p : q);
    uint32_t hb = f2tf32(w);
    lo = f2tf32(w - __uint_as_float(hb));
    return hb;
}

__global__ __launch_bounds__(256, 3) void k_aggmma(const float* __restrict__ adj,
                                                   float* __restrict__ out) {
    __shared__ SmemT sm;
    const int t = threadIdx.x;
    const int bid = blockIdx.x;
    const int jh = bid >> 8;
    const int b  = (bid >> 6) & 3;
    const int h  = (bid >> 3) & 7;
    const int i0 = (bid & 7) * 128;
    const int jbase = jh * 512;
    float* dst = jh ? p1_buf : out;

    const int lane = t & 31, w = t >> 5;
    const int gq = lane >> 2, tid4 = lane & 3;
    const int m0 = w * 16;

    const int r0g = b * NN + i0 + m0 + gq;         // row index (gq)
    const float Lp0 = Lbuf[r0g * 16 + h],      Ln0 = Lbuf[r0g * 16 + 8 + h];
    const float Lp1 = Lbuf[(r0g + 8) * 16 + h], Ln1 = Lbuf[(r0g + 8) * 16 + 8 + h];

    float acc[4][4];
#pragma unroll
    for (int nt = 0; nt < 4; nt++)
#pragma unroll
        for (int c = 0; c < 4; c++) acc[nt][c] = 0.f;

    // prologue: stage chunk 0
    stageG(sm, 0, b, jbase, h, t);
    if (t < 32)
        sm.Rv_s[0][t] = __ldg(&Rv_glob[(b * NN + jbase + t) * NH + h]);

    const float* arow0 = adj + (size_t)r0g * NN;
    const float* arow1 = arow0 + 8 * NN;

#pragma unroll 1
    for (int n = 0; n < 16; n++) {
        const int j0 = jbase + n * 32;
        const int buf = n & 1;

        // prefetch adj scalars for this chunk (quad-coalesced 16B groups)
        float aval[16];
#pragma unroll
        for (int c = 0; c < 8; c++) {
            aval[c]     = __ldg(arow0 + j0 + tid4 + 4 * c);
            aval[8 + c] = __ldg(arow1 + j0 + tid4 + 4 * c);
        }
        __syncthreads();   // chunk n's G/Rv visible; prev reads of buf done

        // stage chunk n+1 into the other buffer (overlaps compute)
        if (n < 15) {
            stageG(sm, buf ^ 1, b, j0 + 32, h, t);
            if (t < 32)
                sm.Rv_s[buf ^ 1][t] =
                    __ldg(&Rv_glob[(b * NN + j0 + 32 + t) * NH + h]);
        }

        // compute A fragments in registers + mma
#pragma unroll
        for (int k = 0; k < 4; k++) {
            float4 rva = sm.Rv_s[buf][8 * k + tid4];
            float4 rvb = sm.Rv_s[buf][8 * k + tid4 + 4];
            uint32_t ah[4], al[4];
            ah[0] = wsplit(Lp0, Ln0, rva, aval[2 * k],     al[0]);
            ah[1] = wsplit(Lp1, Ln1, rva, aval[8 + 2 * k], al[1]);
            ah[2] = wsplit(Lp0, Ln0, rvb, aval[2 * k + 1],     al[2]);
            ah[3] = wsplit(Lp1, Ln1, rvb, aval[8 + 2 * k + 1], al[3]);
#pragma unroll
            for (int nt = 0; nt < 4; nt++) {
                int row = nt * 8 + gq;
                int u = (8 * k + 2 * tid4) ^ (((row >> 4) & 1) << 2);
                float2 bh2 = *reinterpret_cast<const float2*>(&sm.Gh[buf][row][u]);
                float2 bl2 = *reinterpret_cast<const float2*>(&sm.Gl[buf][row][u]);
                uint32_t bh[2] = {__float_as_uint(bh2.x), __float_as_uint(bh2.y)};
                uint32_t bl[2] = {__float_as_uint(bl2.x), __float_as_uint(bl2.y)};
                mma_tf32(acc[nt], ah, bh);
                mma_tf32(acc[nt], ah, bl);
                mma_tf32(acc[nt], al, bh);
            }
        }
    }

    // epilogue: rows m0+gq, m0+gq+8; cols h*32 + nt*8 + 2*tid4
#pragma unroll
    for (int nt = 0; nt < 4; nt++) {
        float* op0 = dst + (size_t)r0g * OUTF + h * 32 + nt * 8 + 2 * tid4;
        float* op1 = op0 + 8 * OUTF;
        *reinterpret_cast<float2*>(op0) = make_float2(acc[nt][0], acc[nt][1]);
        *reinterpret_cast<float2*>(op1) = make_float2(acc[nt][2], acc[nt][3]);
    }
}

// ---------------------------------------------------------------------------
// K4: out += p1   (combine j-halves)
// ---------------------------------------------------------------------------
__global__ __launch_bounds__(256) void k_comb(float* __restrict__ out) {
    int idx = blockIdx.x * 256 + threadIdx.x;    // < BN*OUTF/4
    float4* o4 = reinterpret_cast<float4*>(out);
    const float4* p4 = reinterpret_cast<const float4*>(p1_buf);
    float4 a = o4[idx], b = p4[idx];
    o4[idx] = make_float4(a.x + b.x, a.y + b.y, a.z + b.z, a.w + b.w);
}

// ---------------------------------------------------------------------------
extern "C" void kernel_launch(void* const* d_in, const int* in_sizes, int n_in,
                              void* d_out, int out_size) {
    const float* h_in = (const float*)d_in[0];
    const float* adj  = (const float*)d_in[1];
    const float* W    = (const float*)d_in[2];
    const float* aw   = (const float*)d_in[3];
    float* out = (float*)d_out;

    k_gemm<<<256, 256>>>(h_in, W, aw);
    k_exp<<<BN * NH / 256, 256>>>();
    k_c<<<(BB * NN) / 32, 512>>>(adj);
    k_aggmma<<<512, 256>>>(adj, out);
    k_comb<<<BN * OUTF / 4 / 256, 256>>>(out);
}

// round 11
// speedup vs baseline: 1.2508x; 1.2508x over previous
#include <cuda_runtime.h>
#include <cuda_bf16.h>
#include <cstdint>

#define BB 4
#define NN 1024
#define INF 256
#define OUTF 256
#define NH 8
#define BN (BB*NN)

// ---------------- scratch (allocation-free) ----------------
__device__ float g_buf[BN*OUTF];    // g = h @ W  (4 MB)
__device__ float p1_buf[BN*OUTF];   // j-half-1 partial (4 MB)
__device__ float ELraw[BN*NH];
__device__ float ERraw[BN*NH];
__device__ float Lbuf[BN*16];       // [exp(el) x8, exp(.2el) x8]
__device__ float Rbuf[BN*16];       // [exp(er) x8, exp(.2er) x8]
__device__ float4 Rv_glob[BN*NH];   // (Rp*c, Rn*c, c, 0) per (b,j,h)

typedef unsigned long long u64;

__device__ __forceinline__ void ffma2(u64& d, u64 a, u64 b) {
    asm("fma.rn.f32x2 %0, %1, %2, %0;" : "+l"(d) : "l"(a), "l"(b));
}
union U2 { u64 u; float2 f; };

__device__ __forceinline__ uint32_t bf2u(__nv_bfloat162 v) {
    return *reinterpret_cast<uint32_t*>(&v);
}
__device__ __forceinline__ void mma_bf16(float* d, const uint32_t* a,
                                         const uint32_t* b) {
    asm volatile(
        "mma.sync.aligned.m16n8k16.row.col.f32.bf16.bf16.f32 "
        "{%0,%1,%2,%3}, {%4,%5,%6,%7}, {%8,%9}, {%0,%1,%2,%3};"
        : "+f"(d[0]), "+f"(d[1]), "+f"(d[2]), "+f"(d[3])
        : "r"(a[0]), "r"(a[1]), "r"(a[2]), "r"(a[3]), "r"(b[0]), "r"(b[1]));
}

// ---------------------------------------------------------------------------
// K1: g = X @ W, 64x64 tile, 4x4 micro-tile, f32x2, fused el/er epilogue.
// ---------------------------------------------------------------------------
__global__ __launch_bounds__(256) void k_gemm(const float* __restrict__ X,
                                              const float* __restrict__ W,
                                              const float* __restrict__ aw) {
    __shared__ __align__(16) float2 Xs2[16][64];
    __shared__ __align__(16) float  Ws [16][64];
    const int t = threadIdx.x;
    const int row0 = (blockIdx.x >> 2) * 64;
    const int cb   = (blockIdx.x & 3) * 64;
    const int tx = t & 15, ty = t >> 4;
    const int r0 = ty * 4, c0 = tx * 4;

    u64 acc[4][2];
#pragma unroll
    for (int r = 0; r < 4; r++) { acc[r][0] = 0ull; acc[r][1] = 0ull; }

    const int lr = t >> 2, lk4 = (t & 3) * 4;
    const int wk = t >> 4, wc = (t & 15) * 4;

    for (int k0 = 0; k0 < INF; k0 += 16) {
        float4 xv = *reinterpret_cast<const float4*>(&X[(row0 + lr) * INF + k0 + lk4]);
        float4 wv = *reinterpret_cast<const float4*>(&W[(k0 + wk) * OUTF + cb + wc]);
        __syncthreads();
        Xs2[lk4 + 0][lr] = make_float2(xv.x, xv.x);
        Xs2[lk4 + 1][lr] = make_float2(xv.y, xv.y);
        Xs2[lk4 + 2][lr] = make_float2(xv.z, xv.z);
        Xs2[lk4 + 3][lr] = make_float2(xv.w, xv.w);
        *reinterpret_cast<float4*>(&Ws[wk][wc]) = wv;
        __syncthreads();
#pragma unroll
        for (int kk = 0; kk < 16; kk++) {
            const ulonglong2* xp = reinterpret_cast<const ulonglong2*>(&Xs2[kk][r0]);
            ulonglong2 xa = xp[0], xb = xp[1];
            ulonglong2 wv2 = *reinterpret_cast<const ulonglong2*>(&Ws[kk][c0]);
            ffma2(acc[0][0], xa.x, wv2.x); ffma2(acc[0][1], xa.x, wv2.y);
            ffma2(acc[1][0], xa.y, wv2.x); ffma2(acc[1][1], xa.y, wv2.y);
            ffma2(acc[2][0], xb.x, wv2.x); ffma2(acc[2][1], xb.x, wv2.y);
            ffma2(acc[3][0], xb.y, wv2.x); ffma2(acc[3][1], xb.y, wv2.y);
        }
    }

    const float4* awp = reinterpret_cast<const float4*>(aw);
    float4 aL = awp[tx & 7];
    float4 aR = awp[8 + (tx & 7)];

#pragma unroll
    for (int r = 0; r < 4; r++) {
        U2 a, b; a.u = acc[r][0]; b.u = acc[r][1];
        float4 o = make_float4(a.f.x, a.f.y, b.f.x, b.f.y);
        *reinterpret_cast<float4*>(&g_buf[(row0 + r0 + r) * OUTF + cb + c0]) = o;

        float el = o.x*aL.x + o.y*aL.y + o.z*aL.z + o.w*aL.w;
        float er = o.x*aR.x + o.y*aR.y + o.z*aR.z + o.w*aR.w;
        el += __shfl_xor_sync(0xffffffffu, el, 1);
        el += __shfl_xor_sync(0xffffffffu, el, 2);
        el += __shfl_xor_sync(0xffffffffu, el, 4);
        er += __shfl_xor_sync(0xffffffffu, er, 1);
        er += __shfl_xor_sync(0xffffffffu, er, 2);
        er += __shfl_xor_sync(0xffffffffu, er, 4);
        if ((tx & 7) == 0) {
            int head = (cb >> 5) + (tx >> 3);
            int row = row0 + r0 + r;
            ELraw[row * NH + head] = el;
            ERraw[row * NH + head] = er;
        }
    }
}

// ---------------------------------------------------------------------------
__global__ __launch_bounds__(256) void k_exp() {
    int idx = blockIdx.x * 256 + threadIdx.x;
    int row = idx >> 3, h = idx & 7;
    float el = ELraw[idx], er = ERraw[idx];
    Lbuf[row * 16 + h]     = __expf(el);
    Lbuf[row * 16 + 8 + h] = __expf(0.2f * el);
    Rbuf[row * 16 + h]     = __expf(er);
    Rbuf[row * 16 + 8 + h] = __expf(0.2f * er);
}

// ---------------------------------------------------------------------------
// K2: 1/s[b,j,h]; writes Rv_glob = (Rp*c, Rn*c, c, 0).
// ---------------------------------------------------------------------------
__global__ __launch_bounds__(512) void k_c(const float* __restrict__ adj) {
    __shared__ float ssum[16][32][8];
    const int t = threadIdx.x;
    const int b = blockIdx.x >> 5;
    const int j0 = (blockIdx.x & 31) * 32;
    const int jl = t & 31, ig = t >> 5;

    const float4* rrow = reinterpret_cast<const float4*>(&Rbuf[(b * NN + j0 + jl) * 16]);
    float4 rp0 = rrow[0], rp1 = rrow[1], rn0 = rrow[2], rn1 = rrow[3];
    float EPr[8] = {rp0.x, rp0.y, rp0.z, rp0.w, rp1.x, rp1.y, rp1.z, rp1.w};
    float ENr[8] = {rn0.x, rn0.y, rn0.z, rn0.w, rn1.x, rn1.y, rn1.z, rn1.w};

    float acc[8];
#pragma unroll
    for (int h = 0; h < 8; h++) acc[h] = 0.f;

    const float* adjcol = adj + (size_t)b * NN * NN + j0 + jl;
#pragma unroll 4
    for (int i = ig; i < NN; i += 16) {
        float a = __ldg(adjcol + (size_t)i * NN);
        const float4* lr = reinterpret_cast<const float4*>(&Lbuf[(b * NN + i) * 16]);
        float4 lp0 = __ldg(&lr[0]), lp1 = __ldg(&lr[1]);
        float4 ln0 = __ldg(&lr[2]), ln1 = __ldg(&lr[3]);
        float EPl[8] = {lp0.x, lp0.y, lp0.z, lp0.w, lp1.x, lp1.y, lp1.z, lp1.w};
        float ENl[8] = {ln0.x, ln0.y, ln0.z, ln0.w, ln1.x, ln1.y, ln1.z, ln1.w};
#pragma unroll
        for (int h = 0; h < 8; h++) {
            float p = EPl[h] * EPr[h];
            float q = ENl[h] * ENr[h];
            float w = (p >= 1.0f) ? p : q;
            acc[h] = fmaf(a, w, acc[h]);
        }
    }
#pragma unroll
    for (int h = 0; h < 8; h++) ssum[ig][jl][h] = acc[h];
    __syncthreads();

    if (t < 256) {
        int jl2 = t >> 3, h = t & 7;
        float s = 0.f;
#pragma unroll
        for (int g = 0; g < 16; g++) s += ssum[g][jl2][h];
        float cc = 1.0f / s;
        int row = b * NN + j0 + jl2;
        float Rp = Rbuf[row * 16 + h] * cc;
        float Rn = Rbuf[row * 16 + 8 + h] * cc;
        Rv_glob[row * NH + h] = make_float4(Rp, Rn, cc, 0.f);
    }
}

// ---------------------------------------------------------------------------
// K3 (tensor, bf16 m16n8k16 3-term): k-index permuted so each lane's A cols
// are {4*tid4..+3} (+16 per k16 group) -> adj via LDG.128 and B pairs
// adjacent -> single LDS.64. G packed bf16x2 hi/lo, rows stride 20 words
// (perfect 2-phase LDS.64 banking). Double-buffered.
// ---------------------------------------------------------------------------
#define GSTR 20
struct SmemT {
    uint32_t Gh[2][32][GSTR];   // 5 KB   (16 data words = 16 j-pairs + pad)
    uint32_t Gl[2][32][GSTR];   // 5 KB
    float4   Rv_s[2][32];       // 1 KB
};

__device__ __forceinline__ void stageG(SmemT& sm, int buf, int b, int j0,
                                       int h, int t) {
    const int jj = t >> 3;            // 0..31 (within block; warp: 4w + lane>>3)
    const int d0 = (t & 7) * 4;
    float4 gv = __ldg(reinterpret_cast<const float4*>(
        g_buf + (size_t)(b * NN + j0 + jj) * OUTF + h * 32 + d0));
    float vs[4] = {gv.x, gv.y, gv.z, gv.w};
    uint32_t myhi[4], mylo[4];
#pragma unroll
    for (int e = 0; e < 4; e++) {
        __nv_bfloat16 hb = __float2bfloat16(vs[e]);
        float hf = __bfloat162float(hb);
        __nv_bfloat16 lb = __float2bfloat16(vs[e] - hf);
        myhi[e] = (uint32_t)__bfloat16_as_ushort(hb);
        mylo[e] = (uint32_t)__bfloat16_as_ushort(lb);
    }
    const int p = jj >> 1;
    const bool evenj = (jj & 1) == 0;
#pragma unroll
    for (int e = 0; e < 4; e++) {
        uint32_t phi = __shfl_xor_sync(0xffffffffu, myhi[e], 8);
        uint32_t plo = __shfl_xor_sync(0xffffffffu, mylo[e], 8);
        if (evenj) sm.Gh[buf][d0 + e][p] = myhi[e] | (phi << 16);
        else       sm.Gl[buf][d0 + e][p] = plo | (mylo[e] << 16);
    }
}

__device__ __forceinline__ float selw(float Lp, float Ln, float4 rv) {
    float p = Lp * rv.x;
    float q = Ln * rv.y;
    return (p >= rv.z) ? p : q;
}

__global__ __launch_bounds__(256, 3) void k_aggmma(const float* __restrict__ adj,
                                                   float* __restrict__ out) {
    __shared__ SmemT sm;
    const int t = threadIdx.x;
    const int bid = blockIdx.x;
    const int jh = bid >> 8;
    const int b  = (bid >> 6) & 3;
    const int h  = (bid >> 3) & 7;
    const int i0 = (bid & 7) * 128;
    const int jbase = jh * 512;
    float* dst = jh ? p1_buf : out;

    const int lane = t & 31;
    const int gq = lane >> 2, tid4 = lane & 3;
    const int m0 = (t >> 5) * 16;

    const int r0g = b * NN + i0 + m0 + gq;
    const float Lp0 = Lbuf[r0g * 16 + h],       Ln0 = Lbuf[r0g * 16 + 8 + h];
    const float Lp1 = Lbuf[(r0g + 8) * 16 + h], Ln1 = Lbuf[(r0g + 8) * 16 + 8 + h];

    float acc[4][4];
#pragma unroll
    for (int nt = 0; nt < 4; nt++)
#pragma unroll
        for (int c = 0; c < 4; c++) acc[nt][c] = 0.f;

    // prologue
    stageG(sm, 0, b, jbase, h, t);
    if (t < 32)
        sm.Rv_s[0][t] = __ldg(&Rv_glob[(b * NN + jbase + t) * NH + h]);

    const float* arow0 = adj + (size_t)r0g * NN;
    const float* arow1 = arow0 + 8 * NN;

#pragma unroll 1
    for (int n = 0; n < 16; n++) {
        const int j0 = jbase + n * 32;
        const int buf = n & 1;

        // adj prefetch: 4 x LDG.128 (phys cols 4*tid4..+3, +16; rows gq, gq+8)
        float4 aA[2], aB[2];
        aA[0] = __ldg(reinterpret_cast<const float4*>(arow0 + j0 + 4 * tid4));
        aA[1] = __ldg(reinterpret_cast<const float4*>(arow0 + j0 + 16 + 4 * tid4));
        aB[0] = __ldg(reinterpret_cast<const float4*>(arow1 + j0 + 4 * tid4));
        aB[1] = __ldg(reinterpret_cast<const float4*>(arow1 + j0 + 16 + 4 * tid4));

        __syncthreads();   // chunk n's G/Rv visible; prior reads of buf done

        if (n < 15) {
            stageG(sm, buf ^ 1, b, j0 + 32, h, t);
            if (t < 32)
                sm.Rv_s[buf ^ 1][t] =
                    __ldg(&Rv_glob[(b * NN + j0 + 32 + t) * NH + h]);
        }

#pragma unroll
        for (int kg = 0; kg < 2; kg++) {
            // Rv for this lane's 4 phys cols
            float4 rv0 = sm.Rv_s[buf][kg * 16 + 4 * tid4 + 0];
            float4 rv1 = sm.Rv_s[buf][kg * 16 + 4 * tid4 + 1];
            float4 rv2 = sm.Rv_s[buf][kg * 16 + 4 * tid4 + 2];
            float4 rv3 = sm.Rv_s[buf][kg * 16 + 4 * tid4 + 3];
            const float* avA = &aA[kg].x;
            const float* avB = &aB[kg].x;
            float w0 = avA[0] * selw(Lp0, Ln0, rv0);
            float w1 = avA[1] * selw(Lp0, Ln0, rv1);
            float w2 = avA[2] * selw(Lp0, Ln0, rv2);
            float w3 = avA[3] * selw(Lp0, Ln0, rv3);
            float v0 = avB[0] * selw(Lp1, Ln1, rv0);
            float v1 = avB[1] * selw(Lp1, Ln1, rv1);
            float v2 = avB[2] * selw(Lp1, Ln1, rv2);
            float v3 = avB[3] * selw(Lp1, Ln1, rv3);

            __nv_bfloat162 hw01 = __floats2bfloat162_rn(w0, w1);
            __nv_bfloat162 hw23 = __floats2bfloat162_rn(w2, w3);
            __nv_bfloat162 hv01 = __floats2bfloat162_rn(v0, v1);
            __nv_bfloat162 hv23 = __floats2bfloat162_rn(v2, v3);
            __nv_bfloat162 lw01 = __floats2bfloat162_rn(
                w0 - __low2float(hw01), w1 - __high2float(hw01));
            __nv_bfloat162 lw23 = __floats2bfloat162_rn(
                w2 - __low2float(hw23), w3 - __high2float(hw23));
            __nv_bfloat162 lv01 = __floats2bfloat162_rn(
                v0 - __low2float(hv01), v1 - __high2float(hv01));
            __nv_bfloat162 lv23 = __floats2bfloat162_rn(
                v2 - __low2float(hv23), v3 - __high2float(hv23));

            uint32_t ah[4] = {bf2u(hw01), bf2u(hv01), bf2u(hw23), bf2u(hv23)};
            uint32_t al[4] = {bf2u(lw01), bf2u(lv01), bf2u(lw23), bf2u(lv23)};

#pragma unroll
            for (int nt = 0; nt < 4; nt++) {
                int row = nt * 8 + gq;
                int wofs = 8 * kg + 2 * tid4;
                uint2 bh2 = *reinterpret_cast<const uint2*>(&sm.Gh[buf][row][wofs]);
                uint2 bl2 = *reinterpret_cast<const uint2*>(&sm.Gl[buf][row][wofs]);
                uint32_t bh[2] = {bh2.x, bh2.y};
                uint32_t bl[2] = {bl2.x, bl2.y};
                mma_bf16(acc[nt], ah, bh);
                mma_bf16(acc[nt], ah, bl);
                mma_bf16(acc[nt], al, bh);
            }
        }
    }

    // epilogue: rows m0+gq, m0+gq+8; cols h*32 + nt*8 + 2*tid4
#pragma unroll
    for (int nt = 0; nt < 4; nt++) {
        float* op0 = dst + (size_t)r0g * OUTF + h * 32 + nt * 8 + 2 * tid4;
        float* op1 = op0 + 8 * OUTF;
        *reinterpret_cast<float2*>(op0) = make_float2(acc[nt][0], acc[nt][1]);
        *reinterpret_cast<float2*>(op1) = make_float2(acc[nt][2], acc[nt][3]);
    }
}

// ---------------------------------------------------------------------------
// K4: out += p1   (combine j-halves)
// ---------------------------------------------------------------------------
__global__ __launch_bounds__(256) void k_comb(float* __restrict__ out) {
    int idx = blockIdx.x * 256 + threadIdx.x;    // < BN*OUTF/4
    float4* o4 = reinterpret_cast<float4*>(out);
    const float4* p4 = reinterpret_cast<const float4*>(p1_buf);
    float4 a = o4[idx], b = p4[idx];
    o4[idx] = make_float4(a.x + b.x, a.y + b.y, a.z + b.z, a.w + b.w);
}

// ---------------------------------------------------------------------------
extern "C" void kernel_launch(void* const* d_in, const int* in_sizes, int n_in,
                              void* d_out, int out_size) {
    const float* h_in = (const float*)d_in[0];
    const float* adj  = (const float*)d_in[1];
    const float* W    = (const float*)d_in[2];
    const float* aw   = (const float*)d_in[3];
    float* out = (float*)d_out;

    k_gemm<<<256, 256>>>(h_in, W, aw);
    k_exp<<<BN * NH / 256, 256>>>();
    k_c<<<(BB * NN) / 32, 512>>>(adj);
    k_aggmma<<<512, 256>>>(adj, out);
    k_comb<<<BN * OUTF / 4 / 256, 256>>>(out);
}